// round 2
// baseline (speedup 1.0000x reference)
#include <cuda_runtime.h>
#include <cuda_bf16.h>
#include <cfloat>
#include <cstdint>

// Problem constants
#define NVERT 10242
#define DLEV  4
#define DIM   256
#define HEADS 8
#define HD    32
#define KNBR  8
#define MTOK  (NVERT * DLEV)          // 40968 tokens
#define QSCALE 5.65685424949238f      // sqrt(32): reference divides q by HD^(-0.5)

// Scratch (device globals; allocation inside kernel_launch is forbidden)
__device__ float g_qkv[(size_t)MTOK * 3 * DIM];   // [M, 768] : q(scaled) | k | v
__device__ float g_y[(size_t)MTOK * DIM];         // [M, 256]

// ---------------------------------------------------------------------------
// SGEMM (NT): C[M,N] = A[M,K] * B[N,K]^T + bias[N]
// A,B row-major, K-contiguous. BM=128, BN=64, BK=16, 256 threads, 8x4 microtile.
// SCALEQ: multiply columns [0,256) by QSCALE (q scaling fused into QKV epilogue)
// ---------------------------------------------------------------------------
template <bool SCALEQ>
__global__ __launch_bounds__(256)
void sgemm_nt(const float* __restrict__ A, const float* __restrict__ B,
              const float* __restrict__ bias, float* __restrict__ C,
              int M, int N, int K)
{
    constexpr int BM = 128, BN = 64, BK = 16;
    __shared__ float As[BK][BM + 4];   // stride 132
    __shared__ float Bs[BK][BN + 4];   // stride 68

    const int tid = threadIdx.x;
    const int tx = tid & 15;           // 0..15 -> N
    const int ty = tid >> 4;           // 0..15 -> M
    const int bm = blockIdx.y * BM;
    const int bn = blockIdx.x * BN;

    float acc[8][4];
    #pragma unroll
    for (int i = 0; i < 8; i++)
        #pragma unroll
        for (int j = 0; j < 4; j++) acc[i][j] = 0.f;

    for (int k0 = 0; k0 < K; k0 += BK) {
        // Load A tile: 128x16 = 512 float4, 2 per thread
        #pragma unroll
        for (int it = 0; it < 2; it++) {
            int f = tid + it * 256;
            int row = f >> 2, seg = f & 3;
            int gm = bm + row;
            float4 v = make_float4(0.f, 0.f, 0.f, 0.f);
            if (gm < M)
                v = *(const float4*)(A + (size_t)gm * K + k0 + seg * 4);
            As[seg * 4 + 0][row] = v.x;
            As[seg * 4 + 1][row] = v.y;
            As[seg * 4 + 2][row] = v.z;
            As[seg * 4 + 3][row] = v.w;
        }
        // Load B tile: 64x16 = 256 float4, 1 per thread (N is multiple of 64)
        {
            int row = tid >> 2, seg = tid & 3;
            int gn = bn + row;
            float4 v = *(const float4*)(B + (size_t)gn * K + k0 + seg * 4);
            Bs[seg * 4 + 0][row] = v.x;
            Bs[seg * 4 + 1][row] = v.y;
            Bs[seg * 4 + 2][row] = v.z;
            Bs[seg * 4 + 3][row] = v.w;
        }
        __syncthreads();

        #pragma unroll
        for (int kk = 0; kk < BK; kk++) {
            float a[8], b[4];
            #pragma unroll
            for (int i = 0; i < 8; i++) a[i] = As[kk][ty * 8 + i];
            #pragma unroll
            for (int j = 0; j < 4; j++) b[j] = Bs[kk][tx * 4 + j];
            #pragma unroll
            for (int i = 0; i < 8; i++)
                #pragma unroll
                for (int j = 0; j < 4; j++)
                    acc[i][j] = fmaf(a[i], b[j], acc[i][j]);
        }
        __syncthreads();
    }

    // Epilogue
    #pragma unroll
    for (int i = 0; i < 8; i++) {
        int gm = bm + ty * 8 + i;
        if (gm >= M) continue;
        #pragma unroll
        for (int j = 0; j < 4; j++) {
            int gn = bn + tx * 4 + j;
            float v = acc[i][j] + bias[gn];
            if (SCALEQ && gn < DIM) v *= QSCALE;
            C[(size_t)gm * N + gn] = v;
        }
    }
}

// ---------------------------------------------------------------------------
// Attention: one block per vertex, 256 threads (8 warps).
// Gather q (4x256), k/v (32 rows of 256 = 8 nbrs x 4 levels) into smem.
// Warp handles 4 (h,d) tasks: lane=key for QK+softmax, lane=channel for AV.
// ---------------------------------------------------------------------------
#define KSTR 257   // padded stride for k (conflict-free lane=key reads)

__global__ __launch_bounds__(256)
void attn_kernel(const int* __restrict__ which, const int* __restrict__ mask)
{
    extern __shared__ float sm[];
    float* q_s = sm;                       // 4*256   = 1024
    float* k_s = sm + 4 * DIM;             // 32*257  = 8224
    float* v_s = k_s + 32 * KSTR;          // 32*256  = 8192

    const int n = blockIdx.x;
    const int tid = threadIdx.x;
    const int lane = tid & 31;
    const int w = tid >> 5;

    // Gather q (already scaled)
    {
        ((float4*)q_s)[tid] =
            ((const float4*)(g_qkv + (size_t)(n * 4 + (tid >> 6)) * 768))[tid & 63];
    }
    // Gather k/v: rows w, w+8, w+16, w+24
    #pragma unroll
    for (int r = w; r < 32; r += 8) {
        int nb = which[n * KNBR + (r >> 2)];
        const float* base = g_qkv + (size_t)(nb * 4 + (r & 3)) * 768;
        #pragma unroll
        for (int c4 = lane; c4 < 64; c4 += 32) {
            float4 kv = ((const float4*)(base + DIM))[c4];
            int c = c4 * 4;
            k_s[r * KSTR + c + 0] = kv.x;
            k_s[r * KSTR + c + 1] = kv.y;
            k_s[r * KSTR + c + 2] = kv.z;
            k_s[r * KSTR + c + 3] = kv.w;
            ((float4*)(v_s + r * DIM))[c4] = ((const float4*)(base + 2 * DIM))[c4];
        }
    }
    __syncthreads();

    const unsigned full = 0xffffffffu;
    // mask is int32 (bool coerced by harness); entry per (vertex, neighbor)
    const bool mk = mask[n * KNBR + (lane >> 2)] != 0;

    #pragma unroll
    for (int it = 0; it < 4; it++) {
        int task = w * 4 + it;
        int h = task >> 2, d = task & 3;

        // QK: lane = key index (nbr*4 + lev)
        const float* kp = k_s + lane * KSTR + h * HD;
        const float* qp = q_s + d * DIM + h * HD;
        float acc = 0.f;
        #pragma unroll
        for (int c = 0; c < HD; c++) acc = fmaf(qp[c], kp[c], acc);
        if (!mk) acc = -FLT_MAX;

        // softmax over 32 keys (warp)
        float mx = acc;
        #pragma unroll
        for (int o = 16; o; o >>= 1) mx = fmaxf(mx, __shfl_xor_sync(full, mx, o));
        float e = mk ? __expf(acc - mx) : 0.f;
        float s = e;
        #pragma unroll
        for (int o = 16; o; o >>= 1) s += __shfl_xor_sync(full, s, o);
        float p = e / s;

        // AV: lane = output channel within head
        float o_acc = 0.f;
        const float* vp = v_s + h * HD + lane;
        #pragma unroll
        for (int ke = 0; ke < 32; ke++) {
            float pk = __shfl_sync(full, p, ke);
            o_acc = fmaf(pk, vp[ke * DIM], o_acc);
        }
        g_y[(size_t)(n * 4 + d) * DIM + h * HD + lane] = o_acc;
    }
}

// ---------------------------------------------------------------------------
extern "C" void kernel_launch(void* const* d_in, const int* in_sizes, int n_in,
                              void* d_out, int out_size)
{
    const float* x      = (const float*)d_in[0];
    const int*   which  = (const int*)d_in[1];
    const int*   mask   = (const int*)d_in[2];
    const float* qkv_w  = (const float*)d_in[3];
    const float* qkv_b  = (const float*)d_in[4];
    const float* proj_w = (const float*)d_in[5];
    const float* proj_b = (const float*)d_in[6];
    float*       out    = (float*)d_out;

    float* qkv_ptr = nullptr;
    float* y_ptr   = nullptr;
    cudaGetSymbolAddress((void**)&qkv_ptr, g_qkv);
    cudaGetSymbolAddress((void**)&y_ptr, g_y);

    const int M = MTOK;

    // 1) QKV GEMM: [M,256] x [256,768]^T -> g_qkv, q columns scaled
    {
        dim3 grid(3 * DIM / 64, (M + 127) / 128);
        sgemm_nt<true><<<grid, 256>>>(x, qkv_w, qkv_b, qkv_ptr, M, 3 * DIM, DIM);
    }

    // 2) Attention per vertex
    {
        int smem = (4 * DIM + 32 * KSTR + 32 * DIM) * (int)sizeof(float); // 69760 B
        cudaFuncSetAttribute(attn_kernel, cudaFuncAttributeMaxDynamicSharedMemorySize, smem);
        attn_kernel<<<NVERT, 256, smem>>>(which, mask);
    }

    // 3) Proj GEMM: [M,256] x [256,256]^T -> out
    {
        dim3 grid(DIM / 64, (M + 127) / 128);
        sgemm_nt<false><<<grid, 256>>>(y_ptr, proj_w, proj_b, out, M, DIM, DIM);
    }
}

// round 6
// speedup vs baseline: 1.8860x; 1.8860x over previous
#include <cuda_runtime.h>
#include <cuda_bf16.h>
#include <cfloat>
#include <cstdint>

// Problem constants
#define NVERT 10242
#define DLEV  4
#define DIM   256
#define HEADS 8
#define HD    32
#define KNBR  8
#define MTOK  (NVERT * DLEV)          // 40968 tokens
#define KSPLIT 768                    // split-bf16 K: A=[hi|lo|hi] . B=[hi|hi|lo]
#define QSCALE 5.65685424949238f      // sqrt(32)

// Scratch (device globals; no allocation allowed)
__device__ float          g_qkv[(size_t)MTOK * 3 * DIM];     // [M,768] f32: q|k|v
__device__ __nv_bfloat16  g_xbf[(size_t)MTOK * KSPLIT];      // x split  [hi|lo|hi]
__device__ __nv_bfloat16  g_ybf[(size_t)MTOK * KSPLIT];      // y split  [hi|lo|hi]
__device__ __nv_bfloat16  g_wqkv[(size_t)(3*DIM) * KSPLIT];  // qkv_w split [hi|hi|lo]
__device__ __nv_bfloat16  g_wproj[(size_t)DIM * KSPLIT];     // proj_w split [hi|hi|lo]

// ===========================================================================
// helpers
// ===========================================================================
__device__ __forceinline__ uint32_t smem_u32(const void* p) {
    uint32_t a;
    asm("{ .reg .u64 t; cvta.to.shared.u64 t, %1; cvt.u32.u64 %0, t; }" : "=r"(a) : "l"(p));
    return a;
}
__device__ __forceinline__ void cp_async16(uint32_t saddr, const void* gptr, uint32_t bytes) {
    asm volatile("cp.async.cg.shared.global [%0], [%1], 16, %2;\n"
                 :: "r"(saddr), "l"(gptr), "r"(bytes));
}
__device__ __forceinline__ void cp_commit() {
    asm volatile("cp.async.commit_group;\n" ::: "memory");
}
template <int N>
__device__ __forceinline__ void cp_wait() {
    asm volatile("cp.async.wait_group %0;\n" :: "n"(N) : "memory");
}
__device__ __forceinline__ void ldsm_x4(uint32_t& r0, uint32_t& r1, uint32_t& r2, uint32_t& r3,
                                        uint32_t addr) {
    asm volatile("ldmatrix.sync.aligned.m8n8.x4.shared.b16 {%0,%1,%2,%3}, [%4];"
                 : "=r"(r0), "=r"(r1), "=r"(r2), "=r"(r3) : "r"(addr));
}
__device__ __forceinline__ void mma16816(float* d, const uint32_t* a, const uint32_t* b) {
    asm volatile(
        "mma.sync.aligned.m16n8k16.row.col.f32.bf16.bf16.f32 "
        "{%0,%1,%2,%3}, {%4,%5,%6,%7}, {%8,%9}, {%0,%1,%2,%3};"
        : "+f"(d[0]), "+f"(d[1]), "+f"(d[2]), "+f"(d[3])
        : "r"(a[0]), "r"(a[1]), "r"(a[2]), "r"(a[3]), "r"(b[0]), "r"(b[1]));
}

// ===========================================================================
// bf16 tensor-core GEMM (mma.sync): C[M,N] = A[M,768] . B[N,768]^T + bias
// 128x128 CTA tile, BK=64, 8 warps (2x4) of 64x32 warp tiles,
// cp.async double-buffered, XOR-swizzled smem, fused bias (+q scale).
// ===========================================================================
#define BK 64
#define KITERS (KSPLIT / BK)       // 12
#define TILE_BYTES (128 * BK * 2)  // 16384
#define BUF_BYTES  (2 * TILE_BYTES)

template <bool SCALEQ>
__global__ __launch_bounds__(256, 2)
void gemm_mma(const __nv_bfloat16* __restrict__ A, const __nv_bfloat16* __restrict__ B,
              const float* __restrict__ bias, float* __restrict__ C, int M, int N)
{
    extern __shared__ char sm[];
    const uint32_t smb = smem_u32(sm);
    const int tid  = threadIdx.x;
    const int lane = tid & 31;
    const int w    = tid >> 5;
    const int wm   = w >> 2;           // 0..1
    const int wn   = w & 3;            // 0..3
    const int bm   = blockIdx.y * 128;
    const int bn   = blockIdx.x * 128;

    // ldmatrix lane addressing
    const int a_r0  = wm * 64 + ((lane >> 3) & 1) * 8 + (lane & 7);
    const int a_khi = lane >> 4;
    const int b_r0  = wn * 32 + ((lane >> 4) & 1) * 8 + (lane & 7);
    const int b_khi = (lane >> 3) & 1;

    float acc[4][4][4];
    #pragma unroll
    for (int i = 0; i < 4; i++)
        #pragma unroll
        for (int j = 0; j < 4; j++)
            #pragma unroll
            for (int c = 0; c < 4; c++) acc[i][j][c] = 0.f;

    auto load_tile = [&](int buf, int it) {
        const int k0 = it * BK;
        const uint32_t sA = smb + buf * BUF_BYTES;
        const uint32_t sB = sA + TILE_BYTES;
        #pragma unroll
        for (int i = 0; i < 4; i++) {
            int e = tid + i * 256;
            int r = e >> 3, u = e & 7;
            int gr = bm + r;
            bool ok = gr < M;
            const __nv_bfloat16* ga = A + (size_t)(ok ? gr : 0) * KSPLIT + k0 + u * 8;
            cp_async16(sA + r * 128 + ((u ^ (r & 7)) << 4), ga, ok ? 16u : 0u);
            const __nv_bfloat16* gb = B + (size_t)(bn + r) * KSPLIT + k0 + u * 8;
            cp_async16(sB + r * 128 + ((u ^ (r & 7)) << 4), gb, 16u);
        }
        cp_commit();
    };

    auto compute = [&](int buf) {
        const uint32_t sA = smb + buf * BUF_BYTES;
        const uint32_t sB = sA + TILE_BYTES;
        #pragma unroll
        for (int ks = 0; ks < BK / 16; ks++) {
            uint32_t a[4][4];
            #pragma unroll
            for (int mf = 0; mf < 4; mf++) {
                int row = a_r0 + mf * 16;
                int ku  = ks * 2 + a_khi;
                ldsm_x4(a[mf][0], a[mf][1], a[mf][2], a[mf][3],
                        sA + row * 128 + ((ku ^ (row & 7)) << 4));
            }
            uint32_t b[4][2];
            #pragma unroll
            for (int np = 0; np < 2; np++) {
                int row = b_r0 + np * 16;
                int ku  = ks * 2 + b_khi;
                uint32_t r0, r1, r2, r3;
                ldsm_x4(r0, r1, r2, r3, sB + row * 128 + ((ku ^ (row & 7)) << 4));
                b[np * 2 + 0][0] = r0; b[np * 2 + 0][1] = r1;
                b[np * 2 + 1][0] = r2; b[np * 2 + 1][1] = r3;
            }
            #pragma unroll
            for (int mf = 0; mf < 4; mf++)
                #pragma unroll
                for (int nf = 0; nf < 4; nf++)
                    mma16816(acc[mf][nf], a[mf], b[nf]);
        }
    };

    load_tile(0, 0);
    #pragma unroll 1
    for (int it = 0; it < KITERS; it++) {
        if (it + 1 < KITERS) { load_tile((it + 1) & 1, it + 1); cp_wait<1>(); }
        else                 { cp_wait<0>(); }
        __syncthreads();
        compute(it & 1);
        __syncthreads();
    }

    // Epilogue: fused bias (+ q scale)
    const int gn_base = bn + wn * 32 + (lane & 3) * 2;
    #pragma unroll
    for (int mf = 0; mf < 4; mf++) {
        #pragma unroll
        for (int half = 0; half < 2; half++) {
            int gm = bm + wm * 64 + mf * 16 + (lane >> 2) + half * 8;
            if (gm >= M) continue;
            #pragma unroll
            for (int nf = 0; nf < 4; nf++) {
                int gn = gn_base + nf * 8;
                float v0 = acc[mf][nf][half * 2 + 0] + bias[gn];
                float v1 = acc[mf][nf][half * 2 + 1] + bias[gn + 1];
                if (SCALEQ && gn < DIM) { v0 *= QSCALE; v1 *= QSCALE; }
                *(float2*)(C + (size_t)gm * N + gn) = make_float2(v0, v1);
            }
        }
    }
}

// ===========================================================================
// fp32 -> split-bf16 conversion: src [M,256] -> dst [M,768]
//   B_SIDE=false (A operand): [hi | lo | hi]
//   B_SIDE=true  (B operand): [hi | hi | lo]
// so that A'.B' over K=768 = AhBh + AlBh + AhBl  (drops only AlBl ~ 2^-17)
// ===========================================================================
template <bool B_SIDE>
__global__ void conv_split(const float* __restrict__ src, __nv_bfloat16* __restrict__ dst, int M)
{
    int idx = blockIdx.x * blockDim.x + threadIdx.x;   // one float4 per thread
    if (idx >= M * 64) return;
    int m = idx >> 6, c4 = idx & 63;
    float4 v = ((const float4*)src)[idx];
    __align__(8) __nv_bfloat16 h[4];
    __align__(8) __nv_bfloat16 l[4];
    float f[4] = {v.x, v.y, v.z, v.w};
    #pragma unroll
    for (int j = 0; j < 4; j++) {
        h[j] = __float2bfloat16(f[j]);
        l[j] = __float2bfloat16(f[j] - __bfloat162float(h[j]));
    }
    __nv_bfloat16* base = dst + (size_t)m * KSPLIT + c4 * 4;
    if (B_SIDE) {
        *(uint2*)(base)       = *(uint2*)h;
        *(uint2*)(base + 256) = *(uint2*)h;
        *(uint2*)(base + 512) = *(uint2*)l;
    } else {
        *(uint2*)(base)       = *(uint2*)h;
        *(uint2*)(base + 256) = *(uint2*)l;
        *(uint2*)(base + 512) = *(uint2*)h;
    }
}

// ===========================================================================
// Attention: one block per vertex, 256 threads. Emits split-bf16 y' (A-side).
// ===========================================================================
#define KSTR 257

__global__ __launch_bounds__(256)
void attn_kernel(const int* __restrict__ which, const int* __restrict__ mask)
{
    extern __shared__ float smf[];
    float* q_s = smf;                      // 4*256
    float* k_s = smf + 4 * DIM;            // 32*257
    float* v_s = k_s + 32 * KSTR;          // 32*256

    const int n = blockIdx.x;
    const int tid = threadIdx.x;
    const int lane = tid & 31;
    const int w = tid >> 5;

    ((float4*)q_s)[tid] =
        ((const float4*)(g_qkv + (size_t)(n * 4 + (tid >> 6)) * 768))[tid & 63];

    #pragma unroll
    for (int r = w; r < 32; r += 8) {
        int nb = which[n * KNBR + (r >> 2)];
        const float* base = g_qkv + (size_t)(nb * 4 + (r & 3)) * 768;
        #pragma unroll
        for (int c4 = lane; c4 < 64; c4 += 32) {
            float4 kv = ((const float4*)(base + DIM))[c4];
            int c = c4 * 4;
            k_s[r * KSTR + c + 0] = kv.x;
            k_s[r * KSTR + c + 1] = kv.y;
            k_s[r * KSTR + c + 2] = kv.z;
            k_s[r * KSTR + c + 3] = kv.w;
            ((float4*)(v_s + r * DIM))[c4] = ((const float4*)(base + 2 * DIM))[c4];
        }
    }
    __syncthreads();

    const unsigned full = 0xffffffffu;
    const bool mk = mask[n * KNBR + (lane >> 2)] != 0;

    #pragma unroll
    for (int it = 0; it < 4; it++) {
        int task = w * 4 + it;
        int h = task >> 2, d = task & 3;

        const float* kp = k_s + lane * KSTR + h * HD;
        const float* qp = q_s + d * DIM + h * HD;
        float acc = 0.f;
        #pragma unroll
        for (int c = 0; c < HD; c++) acc = fmaf(qp[c], kp[c], acc);
        if (!mk) acc = -FLT_MAX;

        float mx = acc;
        #pragma unroll
        for (int o = 16; o; o >>= 1) mx = fmaxf(mx, __shfl_xor_sync(full, mx, o));
        float e = mk ? __expf(acc - mx) : 0.f;
        float s = e;
        #pragma unroll
        for (int o = 16; o; o >>= 1) s += __shfl_xor_sync(full, s, o);
        float p = e / s;

        float o_acc = 0.f;
        const float* vp = v_s + h * HD + lane;
        #pragma unroll
        for (int ke = 0; ke < 32; ke++) {
            float pk = __shfl_sync(full, p, ke);
            o_acc = fmaf(pk, vp[ke * DIM], o_acc);
        }
        // A-side split: [hi | lo | hi]
        __nv_bfloat16 hi = __float2bfloat16(o_acc);
        __nv_bfloat16 lo = __float2bfloat16(o_acc - __bfloat162float(hi));
        __nv_bfloat16* yb = g_ybf + (size_t)(n * 4 + d) * KSPLIT + h * HD + lane;
        yb[0]   = hi;
        yb[256] = lo;
        yb[512] = hi;
    }
}

// ===========================================================================
extern "C" void kernel_launch(void* const* d_in, const int* in_sizes, int n_in,
                              void* d_out, int out_size)
{
    const float* x      = (const float*)d_in[0];
    const int*   which  = (const int*)d_in[1];
    const int*   mask   = (const int*)d_in[2];
    const float* qkv_w  = (const float*)d_in[3];
    const float* qkv_b  = (const float*)d_in[4];
    const float* proj_w = (const float*)d_in[5];
    const float* proj_b = (const float*)d_in[6];
    float*       out    = (float*)d_out;

    float *qkv_ptr = nullptr;
    __nv_bfloat16 *xbf = nullptr, *ybf = nullptr, *wqkv = nullptr, *wproj = nullptr;
    cudaGetSymbolAddress((void**)&qkv_ptr, g_qkv);
    cudaGetSymbolAddress((void**)&xbf,  g_xbf);
    cudaGetSymbolAddress((void**)&ybf,  g_ybf);
    cudaGetSymbolAddress((void**)&wqkv, g_wqkv);
    cudaGetSymbolAddress((void**)&wproj, g_wproj);

    const int M = MTOK;
    const int GEMM_SMEM = 2 * BUF_BYTES;   // 65536

    // 0) split-bf16 conversions: A-side [hi|lo|hi], B-side [hi|hi|lo]
    conv_split<false><<<(M * 64 + 255) / 256, 256>>>(x, xbf, M);
    conv_split<true><<<(3 * DIM * 64 + 255) / 256, 256>>>(qkv_w, wqkv, 3 * DIM);
    conv_split<true><<<(DIM * 64 + 255) / 256, 256>>>(proj_w, wproj, DIM);

    // 1) QKV GEMM (mma.sync bf16): [M,768] x [768,768]^T -> f32, q scaled
    {
        cudaFuncSetAttribute(gemm_mma<true>, cudaFuncAttributeMaxDynamicSharedMemorySize, GEMM_SMEM);
        dim3 grid(3 * DIM / 128, (M + 127) / 128);
        gemm_mma<true><<<grid, 256, GEMM_SMEM>>>(xbf, wqkv, qkv_b, qkv_ptr, M, 3 * DIM);
    }

    // 2) Attention per vertex (emits split-bf16 y')
    {
        int smem = (4 * DIM + 32 * KSTR + 32 * DIM) * (int)sizeof(float);
        cudaFuncSetAttribute(attn_kernel, cudaFuncAttributeMaxDynamicSharedMemorySize, smem);
        attn_kernel<<<NVERT, 256, smem>>>(which, mask);
    }

    // 3) Proj GEMM (mma.sync bf16) -> d_out
    {
        cudaFuncSetAttribute(gemm_mma<false>, cudaFuncAttributeMaxDynamicSharedMemorySize, GEMM_SMEM);
        dim3 grid(DIM / 128, (M + 127) / 128);
        gemm_mma<false><<<grid, 256, GEMM_SMEM>>>(ybf, wproj, proj_b, out, M, DIM);
    }
}